// round 8
// baseline (speedup 1.0000x reference)
#include <cuda_runtime.h>
#include <cstdint>

#define N_SAMPLES   8192
#define CODE_LEN    128
#define NUM_CLASSES 1000
#define NB_MAIN     1024   // k_main: 1024 blocks x 256 thr = 8192 warps (1/sample)
#define NB_MIN      128    // k_min : 128 blocks x 256 thr, 64 samples/block

// ---- device scratch (zero-init at load; self-cleaning across graph replays) ----
__device__ unsigned d_used[NUM_CLASSES];     // set in k_main, zeroed by its last block
__device__ uint4    d_cwbits[NUM_CLASSES];
__device__ uint4    d_compact[NUM_CLASSES];  // dense used-codeword bits (k_main last block)
__device__ int      d_ucount;
__device__ uint4    d_predbits[N_SAMPLES];
__device__ float    d_bce_part[NB_MAIN];
__device__ unsigned d_sig_part[NB_MIN];
__device__ int      d_done_main;             // reset by k_main last block
__device__ int      d_done_min;              // reset by k_min  last block

__device__ __forceinline__ unsigned pack_nib(float4 v) {
    return (unsigned)(v.x > 0.5f)
         | ((unsigned)(v.y > 0.5f) << 1)
         | ((unsigned)(v.z > 0.5f) << 2)
         | ((unsigned)(v.w > 0.5f) << 3);
}

// ---------------------------------------------------------------------------
// K1: codeword bit-pack + per-sample pred pack, used-mark, BCE row sum.
//     Last block additionally compacts the used codeword set (threadfence
//     reduction pattern) so k_min blocks need no per-block ballots.
__global__ void k_main(const float* __restrict__ out_p,
                       const float* __restrict__ cw,
                       const int*   __restrict__ tgt) {
    __shared__ float wsum[8];
    __shared__ int   s_last;
    __shared__ int   s_cnt;
    int gw   = (blockIdx.x * blockDim.x + threadIdx.x) >> 5;  // 0..8191
    int lane = threadIdx.x & 31;
    int wid  = threadIdx.x >> 5;
    int tid  = threadIdx.x;

    // --- pack one codeword (warp-uniform branch) ---
    if (gw < NUM_CLASSES) {
        float4 v = reinterpret_cast<const float4*>(cw + (size_t)gw * CODE_LEN)[lane];
        unsigned nib = pack_nib(v);
        unsigned wi = lane >> 3, sh = (lane & 7) * 4;
        unsigned w0 = __reduce_or_sync(0xffffffffu, wi == 0 ? (nib << sh) : 0u);
        unsigned w1 = __reduce_or_sync(0xffffffffu, wi == 1 ? (nib << sh) : 0u);
        unsigned w2 = __reduce_or_sync(0xffffffffu, wi == 2 ? (nib << sh) : 0u);
        unsigned w3 = __reduce_or_sync(0xffffffffu, wi == 3 ? (nib << sh) : 0u);
        if (lane == 0) d_cwbits[gw] = make_uint4(w0, w1, w2, w3);
    }

    // --- per-sample work (gw < 8192 by grid construction) ---
    int t  = tgt[gw];
    int tc = (t < 0) ? 0 : ((t >= NUM_CLASSES) ? NUM_CLASSES - 1 : t);

    float4 v = reinterpret_cast<const float4*>(out_p + (size_t)gw * CODE_LEN)[lane];
    unsigned nib = pack_nib(v);
    unsigned wi = lane >> 3, sh = (lane & 7) * 4;
    unsigned w0 = __reduce_or_sync(0xffffffffu, wi == 0 ? (nib << sh) : 0u);
    unsigned w1 = __reduce_or_sync(0xffffffffu, wi == 1 ? (nib << sh) : 0u);
    unsigned w2 = __reduce_or_sync(0xffffffffu, wi == 2 ? (nib << sh) : 0u);
    unsigned w3 = __reduce_or_sync(0xffffffffu, wi == 3 ? (nib << sh) : 0u);
    if (lane == 0) {
        d_predbits[gw] = make_uint4(w0, w1, w2, w3);
        d_used[tc] = 1u;
    }

    // BCE from codeword floats (coalesced 512B row, L2-resident table)
    float4 c4 = reinterpret_cast<const float4*>(cw + (size_t)tc * CODE_LEN)[lane];
    float bce = 0.0f;
    bce += (c4.x > 0.5f) ? -logf(v.x) : -log1pf(-v.x);
    bce += (c4.y > 0.5f) ? -logf(v.y) : -log1pf(-v.y);
    bce += (c4.z > 0.5f) ? -logf(v.z) : -log1pf(-v.z);
    bce += (c4.w > 0.5f) ? -logf(v.w) : -log1pf(-v.w);

    #pragma unroll
    for (int off = 16; off > 0; off >>= 1)
        bce += __shfl_down_sync(0xffffffffu, bce, off);
    if (lane == 0) wsum[wid] = bce;
    __syncthreads();
    if (tid == 0) {
        float s = 0.0f;
        #pragma unroll
        for (int w = 0; w < 8; w++) s += wsum[w];
        d_bce_part[blockIdx.x] = s;
        __threadfence();
        int old = atomicAdd(&d_done_main, 1);
        s_last = (old == NB_MAIN - 1);
        s_cnt  = 0;
    }
    __syncthreads();

    // --- last block: compact used codewords, reset state for next replay ---
    if (s_last) {
        #pragma unroll
        for (int c = tid; c < 1024; c += 256) {
            bool p = (c < NUM_CLASSES) && (d_used[c] != 0u);
            unsigned bal = __ballot_sync(0xffffffffu, p);
            int base;
            if (lane == 0) base = atomicAdd(&s_cnt, __popc(bal));
            base = __shfl_sync(0xffffffffu, base, 0);
            if (p) {
                int pos = base + __popc(bal & ((1u << lane) - 1u));
                d_compact[pos] = d_cwbits[c];
            }
        }
        __syncthreads();
        if (tid == 0) { d_ucount = s_cnt; d_done_main = 0; }
        for (int c = tid; c < NUM_CLASSES; c += 256) d_used[c] = 0u;
    }
}

__device__ __forceinline__ unsigned ham4(uint4 a, uint4 b) {
    return __popc(a.x ^ b.x) + __popc(a.y ^ b.y)
         + __popc(a.z ^ b.z) + __popc(a.w ^ b.w);
}

// ---------------------------------------------------------------------------
// K2: 64 samples/block. Each thread owns 4 samples and scans a 1/16 slice of
//     the compacted list: one LDS feeds 4 independent ham4 chains (ALU-bound).
__global__ void __launch_bounds__(256) k_min(float* __restrict__ out) {
    __shared__ uint4    cwl[NUM_CLASSES];
    __shared__ unsigned ured[8];
    __shared__ float    fred[8];
    __shared__ int      s_last;

    int tid  = threadIdx.x;
    int lane = tid & 31, wid = tid >> 5;
    int U = d_ucount;

    for (int k = tid; k < U; k += 256) cwl[k] = d_compact[k];   // coalesced
    __syncthreads();

    int sub = tid & 15;              // list slice
    int grp = tid >> 4;              // 16 groups x 4 samples = 64 samples
    int s   = blockIdx.x * 64 + grp * 4;
    uint4 x0 = d_predbits[s + 0];
    uint4 x1 = d_predbits[s + 1];
    uint4 x2 = d_predbits[s + 2];
    uint4 x3 = d_predbits[s + 3];

    unsigned m0 = 0xffffffffu, m1 = 0xffffffffu, m2 = 0xffffffffu, m3 = 0xffffffffu;
    for (int k = sub; k < U; k += 16) {
        uint4 c = cwl[k];
        m0 = min(m0, ham4(x0, c));
        m1 = min(m1, ham4(x1, c));
        m2 = min(m2, ham4(x2, c));
        m3 = min(m3, ham4(x3, c));
    }
    // combine the 16 list-slices (xor masks stay within each 16-lane half)
    #pragma unroll
    for (int off = 1; off < 16; off <<= 1) {
        m0 = min(m0, __shfl_xor_sync(0xffffffffu, m0, off));
        m1 = min(m1, __shfl_xor_sync(0xffffffffu, m1, off));
        m2 = min(m2, __shfl_xor_sync(0xffffffffu, m2, off));
        m3 = min(m3, __shfl_xor_sync(0xffffffffu, m3, off));
    }

    unsigned v = (sub == 0) ? (m0 + m1 + m2 + m3) : 0u;
    #pragma unroll
    for (int off = 16; off > 0; off >>= 1)
        v += __shfl_down_sync(0xffffffffu, v, off);
    if (lane == 0) ured[wid] = v;
    __syncthreads();
    if (tid == 0) {
        unsigned tot = 0;
        #pragma unroll
        for (int w = 0; w < 8; w++) tot += ured[w];
        d_sig_part[blockIdx.x] = tot;
        __threadfence();
        int old = atomicAdd(&d_done_min, 1);
        s_last = (old == NB_MIN - 1);
    }
    __syncthreads();

    // --- last block: final reduction + output + reset ---
    if (s_last) {
        float fb = 0.0f;
        for (int i = tid; i < NB_MAIN; i += 256) fb += d_bce_part[i];
        unsigned sg = (tid < NB_MIN) ? d_sig_part[tid] : 0u;
        #pragma unroll
        for (int off = 16; off > 0; off >>= 1) {
            fb += __shfl_down_sync(0xffffffffu, fb, off);
            sg += __shfl_down_sync(0xffffffffu, sg, off);
        }
        if (lane == 0) { fred[wid] = fb; ured[wid] = sg; }
        __syncthreads();
        if (tid == 0) {
            float ftot = 0.0f; unsigned stot = 0;
            #pragma unroll
            for (int w = 0; w < 8; w++) { ftot += fred[w]; stot += ured[w]; }
            out[0] = (ftot + (float)CODE_LEN * (float)stot)
                   / (float)(N_SAMPLES * CODE_LEN);
            d_done_min = 0;
        }
    }
}

// ---------------------------------------------------------------------------
extern "C" void kernel_launch(void* const* d_in, const int* in_sizes, int n_in,
                              void* d_out, int out_size) {
    const float* out_p = (const float*)d_in[0];   // [8192,128] float32
    const float* cw_p  = (const float*)d_in[1];   // [1000,128] float32
    const int*   tgt_p = (const int*)d_in[2];     // [8192] int32

    k_main<<<NB_MAIN, 256>>>(out_p, cw_p, tgt_p);
    k_min<<<NB_MIN, 256>>>((float*)d_out);
}

// round 9
// speedup vs baseline: 1.2737x; 1.2737x over previous
#include <cuda_runtime.h>
#include <cstdint>

#define N_SAMPLES   8192
#define CODE_LEN    128
#define NUM_CLASSES 1000
#define NB_MAIN     1024   // k_main: 1024 blocks x 256 thr = 8192 warps (1/sample)
#define NB_MIN      512    // k_min : 512 blocks x 256 thr, 16 samples/block
#define PEN_UNUSED  512u   // > max Hamming distance (128)

// ---- device scratch (zero-init at load; self-cleaning across graph replays) ----
__device__ unsigned d_used[NUM_CLASSES];     // set in k_main, zeroed by k_min last block
__device__ uint4    d_cwbits[NUM_CLASSES];
__device__ uint4    d_predbits[N_SAMPLES];
__device__ float    d_bce_part[NB_MAIN];
__device__ unsigned d_sig_part[NB_MIN];
__device__ int      d_done_min;              // reset by k_min last block

__device__ __forceinline__ unsigned pack_nib(float4 v) {
    return (unsigned)(v.x > 0.5f)
         | ((unsigned)(v.y > 0.5f) << 1)
         | ((unsigned)(v.z > 0.5f) << 2)
         | ((unsigned)(v.w > 0.5f) << 3);
}

// ---------------------------------------------------------------------------
// K1 (R6 form): codeword bit-pack (warps 0..999) + per-sample pred pack,
//     used-mark, BCE row sum. No tail work.
__global__ void k_main(const float* __restrict__ out_p,
                       const float* __restrict__ cw,
                       const int*   __restrict__ tgt) {
    __shared__ float wsum[8];
    int gw   = (blockIdx.x * blockDim.x + threadIdx.x) >> 5;  // 0..8191
    int lane = threadIdx.x & 31;
    int wid  = threadIdx.x >> 5;

    // --- pack one codeword (warp-uniform branch) ---
    if (gw < NUM_CLASSES) {
        float4 v = reinterpret_cast<const float4*>(cw + (size_t)gw * CODE_LEN)[lane];
        unsigned nib = pack_nib(v);
        unsigned wi = lane >> 3, sh = (lane & 7) * 4;
        unsigned w0 = __reduce_or_sync(0xffffffffu, wi == 0 ? (nib << sh) : 0u);
        unsigned w1 = __reduce_or_sync(0xffffffffu, wi == 1 ? (nib << sh) : 0u);
        unsigned w2 = __reduce_or_sync(0xffffffffu, wi == 2 ? (nib << sh) : 0u);
        unsigned w3 = __reduce_or_sync(0xffffffffu, wi == 3 ? (nib << sh) : 0u);
        if (lane == 0) d_cwbits[gw] = make_uint4(w0, w1, w2, w3);
    }

    // --- per-sample work (gw < 8192 by grid construction) ---
    int t  = tgt[gw];
    int tc = (t < 0) ? 0 : ((t >= NUM_CLASSES) ? NUM_CLASSES - 1 : t);

    float4 v = reinterpret_cast<const float4*>(out_p + (size_t)gw * CODE_LEN)[lane];
    unsigned nib = pack_nib(v);
    unsigned wi = lane >> 3, sh = (lane & 7) * 4;
    unsigned w0 = __reduce_or_sync(0xffffffffu, wi == 0 ? (nib << sh) : 0u);
    unsigned w1 = __reduce_or_sync(0xffffffffu, wi == 1 ? (nib << sh) : 0u);
    unsigned w2 = __reduce_or_sync(0xffffffffu, wi == 2 ? (nib << sh) : 0u);
    unsigned w3 = __reduce_or_sync(0xffffffffu, wi == 3 ? (nib << sh) : 0u);
    if (lane == 0) {
        d_predbits[gw] = make_uint4(w0, w1, w2, w3);
        d_used[tc] = 1u;
    }

    // BCE from codeword floats (coalesced 512B row, L2-resident table)
    float4 c4 = reinterpret_cast<const float4*>(cw + (size_t)tc * CODE_LEN)[lane];
    float bce = 0.0f;
    bce += (c4.x > 0.5f) ? -logf(v.x) : -log1pf(-v.x);
    bce += (c4.y > 0.5f) ? -logf(v.y) : -log1pf(-v.y);
    bce += (c4.z > 0.5f) ? -logf(v.z) : -log1pf(-v.z);
    bce += (c4.w > 0.5f) ? -logf(v.w) : -log1pf(-v.w);

    #pragma unroll
    for (int off = 16; off > 0; off >>= 1)
        bce += __shfl_down_sync(0xffffffffu, bce, off);
    if (lane == 0) wsum[wid] = bce;
    __syncthreads();
    if (wid == 0) {
        float s = (lane < 8) ? wsum[lane] : 0.0f;
        #pragma unroll
        for (int off = 4; off > 0; off >>= 1)
            s += __shfl_down_sync(0xffffffffu, s, off);
        if (lane == 0) d_bce_part[blockIdx.x] = s;
    }
}

__device__ __forceinline__ unsigned ham4(uint4 a, uint4 b) {
    return __popc(a.x ^ b.x) + __popc(a.y ^ b.y)
         + __popc(a.z ^ b.z) + __popc(a.w ^ b.w);
}

// ---------------------------------------------------------------------------
// K2: 512 blocks x 256 thr, 16 samples/block. Warp layout: lane&15 = list
//     slice, lane>>4 = sample. Fixed-trip loop over ALL 1000 codewords with
//     a +512 penalty on unused ones (min over used == min over penalized all).
__global__ void __launch_bounds__(256) k_min(float* __restrict__ out) {
    __shared__ uint4    cwl[NUM_CLASSES];
    __shared__ unsigned pen[NUM_CLASSES];
    __shared__ unsigned ured[8];
    __shared__ float    fred[8];
    __shared__ int      s_last;

    int tid  = threadIdx.x;
    int lane = tid & 31, wid = tid >> 5;

    for (int k = tid; k < NUM_CLASSES; k += 256) {
        cwl[k] = d_cwbits[k];                         // coalesced 16B
        pen[k] = (d_used[k] ? 0u : PEN_UNUSED);
    }
    __syncthreads();

    int sub = lane & 15;                              // list slice
    int s   = blockIdx.x * 16 + wid * 2 + (lane >> 4);
    uint4 x = d_predbits[s];

    unsigned mn = 0xffffffffu;
    #pragma unroll 4
    for (int k = sub; k < NUM_CLASSES; k += 16)
        mn = min(mn, ham4(x, cwl[k]) + pen[k]);

    // combine 16 slices (xor masks stay within each 16-lane half)
    #pragma unroll
    for (int off = 1; off < 16; off <<= 1)
        mn = min(mn, __shfl_xor_sync(0xffffffffu, mn, off));

    // block sigma sum: one contribution per sample (sub==0 lanes)
    unsigned v = (sub == 0) ? mn : 0u;
    #pragma unroll
    for (int off = 16; off > 0; off >>= 1)
        v += __shfl_down_sync(0xffffffffu, v, off);
    if (lane == 0) ured[wid] = v;
    __syncthreads();
    if (tid == 0) {
        unsigned tot = 0;
        #pragma unroll
        for (int w = 0; w < 8; w++) tot += ured[w];
        d_sig_part[blockIdx.x] = tot;
        __threadfence();
        int old = atomicAdd(&d_done_min, 1);
        s_last = (old == NB_MIN - 1);
    }
    __syncthreads();

    // --- last block: final reduction + output + state reset ---
    if (s_last) {
        float fb = 0.0f;
        for (int i = tid; i < NB_MAIN; i += 256) fb += d_bce_part[i];
        unsigned sg = 0u;
        for (int i = tid; i < NB_MIN; i += 256) sg += d_sig_part[i];
        #pragma unroll
        for (int off = 16; off > 0; off >>= 1) {
            fb += __shfl_down_sync(0xffffffffu, fb, off);
            sg += __shfl_down_sync(0xffffffffu, sg, off);
        }
        if (lane == 0) { fred[wid] = fb; ured[wid] = sg; }
        __syncthreads();
        if (tid == 0) {
            float ftot = 0.0f; unsigned stot = 0;
            #pragma unroll
            for (int w = 0; w < 8; w++) { ftot += fred[w]; stot += ured[w]; }
            out[0] = (ftot + (float)CODE_LEN * (float)stot)
                   / (float)(N_SAMPLES * CODE_LEN);
            d_done_min = 0;                  // reset for next replay
        }
        for (int c = tid; c < NUM_CLASSES; c += 256)
            d_used[c] = 0u;                  // reset for next replay (safe: all
                                             // blocks read d_used before their
                                             // d_done_min atomic)
    }
}

// ---------------------------------------------------------------------------
extern "C" void kernel_launch(void* const* d_in, const int* in_sizes, int n_in,
                              void* d_out, int out_size) {
    const float* out_p = (const float*)d_in[0];   // [8192,128] float32
    const float* cw_p  = (const float*)d_in[1];   // [1000,128] float32
    const int*   tgt_p = (const int*)d_in[2];     // [8192] int32

    k_main<<<NB_MAIN, 256>>>(out_p, cw_p, tgt_p);
    k_min<<<NB_MIN, 256>>>((float*)d_out);
}

// round 11
// speedup vs baseline: 1.4401x; 1.1306x over previous
#include <cuda_runtime.h>
#include <cstdint>

#define N_SAMPLES   8192
#define CODE_LEN    128
#define NUM_CLASSES 1000
#define NB_MAIN     1024   // k_main: 1024 blocks x 256 thr = 8192 warps (1/sample)
#define NB_MIN      1024   // k_min : (8192/16 samples) x 2 class-halves
#define HALF_CW     500
#define HALF_PAD    512    // padded to multiple of 16

// ---- device scratch (zero-init at load; self-cleaning across graph replays) ----
__device__ unsigned d_used[NUM_CLASSES];   // set in k_main, zeroed by k_min last block
__device__ uint4    d_cwbits[NUM_CLASSES];
__device__ uint4    d_predbits[N_SAMPLES];
__device__ unsigned d_mn[N_SAMPLES];       // per-sample min; re-inited by k_main
__device__ float    d_bce_part[NB_MAIN];
__device__ int      d_done_min;            // reset by k_min last block

__device__ __forceinline__ unsigned pack_nib(float4 v) {
    return (unsigned)(v.x > 0.5f)
         | ((unsigned)(v.y > 0.5f) << 1)
         | ((unsigned)(v.z > 0.5f) << 2)
         | ((unsigned)(v.w > 0.5f) << 3);
}

// ---------------------------------------------------------------------------
// K1: codeword bit-pack (warps 0..999) + per-sample pred pack, used-mark,
//     fast-log BCE row sum. Also re-initializes d_mn for this replay.
__global__ void k_main(const float* __restrict__ out_p,
                       const float* __restrict__ cw,
                       const int*   __restrict__ tgt) {
    __shared__ float wsum[8];
    int gw   = (blockIdx.x * blockDim.x + threadIdx.x) >> 5;  // 0..8191
    int lane = threadIdx.x & 31;
    int wid  = threadIdx.x >> 5;

    // re-init per-sample min slots (8 per block)
    if (threadIdx.x < 8)
        d_mn[blockIdx.x * 8 + threadIdx.x] = 0xffffffffu;

    // --- pack one codeword (warp-uniform branch) ---
    if (gw < NUM_CLASSES) {
        float4 v = reinterpret_cast<const float4*>(cw + (size_t)gw * CODE_LEN)[lane];
        unsigned nib = pack_nib(v);
        unsigned wi = lane >> 3, sh = (lane & 7) * 4;
        unsigned w0 = __reduce_or_sync(0xffffffffu, wi == 0 ? (nib << sh) : 0u);
        unsigned w1 = __reduce_or_sync(0xffffffffu, wi == 1 ? (nib << sh) : 0u);
        unsigned w2 = __reduce_or_sync(0xffffffffu, wi == 2 ? (nib << sh) : 0u);
        unsigned w3 = __reduce_or_sync(0xffffffffu, wi == 3 ? (nib << sh) : 0u);
        if (lane == 0) d_cwbits[gw] = make_uint4(w0, w1, w2, w3);
    }

    // --- per-sample work (gw < 8192 by grid construction) ---
    int t  = tgt[gw];
    int tc = (t < 0) ? 0 : ((t >= NUM_CLASSES) ? NUM_CLASSES - 1 : t);

    float4 v = reinterpret_cast<const float4*>(out_p + (size_t)gw * CODE_LEN)[lane];
    unsigned nib = pack_nib(v);
    unsigned wi = lane >> 3, sh = (lane & 7) * 4;
    unsigned w0 = __reduce_or_sync(0xffffffffu, wi == 0 ? (nib << sh) : 0u);
    unsigned w1 = __reduce_or_sync(0xffffffffu, wi == 1 ? (nib << sh) : 0u);
    unsigned w2 = __reduce_or_sync(0xffffffffu, wi == 2 ? (nib << sh) : 0u);
    unsigned w3 = __reduce_or_sync(0xffffffffu, wi == 3 ? (nib << sh) : 0u);
    if (lane == 0) {
        d_predbits[gw] = make_uint4(w0, w1, w2, w3);
        d_used[tc] = 1u;
    }

    // BCE via MUFU fast log: -log(b ? v : 1-v). |err| ~1e-4 abs, tol 1e-3,
    // and the integer-exact sigma term dominates the mean.
    float4 c4 = reinterpret_cast<const float4*>(cw + (size_t)tc * CODE_LEN)[lane];
    float a0 = (c4.x > 0.5f) ? v.x : (1.0f - v.x);
    float a1 = (c4.y > 0.5f) ? v.y : (1.0f - v.y);
    float a2 = (c4.z > 0.5f) ? v.z : (1.0f - v.z);
    float a3 = (c4.w > 0.5f) ? v.w : (1.0f - v.w);
    float bce = -(__logf(a0) + __logf(a1) + __logf(a2) + __logf(a3));

    #pragma unroll
    for (int off = 16; off > 0; off >>= 1)
        bce += __shfl_down_sync(0xffffffffu, bce, off);
    if (lane == 0) wsum[wid] = bce;
    __syncthreads();
    if (wid == 0) {
        float s = (lane < 8) ? wsum[lane] : 0.0f;
        #pragma unroll
        for (int off = 4; off > 0; off >>= 1)
            s += __shfl_down_sync(0xffffffffu, s, off);
        if (lane == 0) d_bce_part[blockIdx.x] = s;
    }
}

__device__ __forceinline__ unsigned ham4(uint4 a, uint4 b) {
    return __popc(a.x ^ b.x) + __popc(a.y ^ b.y)
         + __popc(a.z ^ b.z) + __popc(a.w ^ b.w);
}

// ---------------------------------------------------------------------------
// K2: 1024 blocks x 256 thr. Block = 16 samples x one class-half (500 classes
//     padded to 512). Unused/pad slots are filled with a known-USED codeword
//     (codewords[target[0]]) so min over the multiset == min over used set —
//     no penalty loads in the inner loop. Cross-half combine via atomicMin.
__global__ void __launch_bounds__(256) k_min(float* __restrict__ out,
                                             const int* __restrict__ tgt) {
    __shared__ uint4    cwl[HALF_PAD];
    __shared__ float    fred[8];
    __shared__ unsigned ured[8];
    __shared__ int      s_last;

    int tid  = threadIdx.x;
    int lane = tid & 31, wid = tid >> 5;
    int h     = blockIdx.x & 1;                  // class half
    int sbase = (blockIdx.x >> 1) * 16;          // sample base

    // fallback = codeword of a guaranteed-used class
    int t0 = tgt[0];
    int fb = (t0 < 0) ? 0 : ((t0 >= NUM_CLASSES) ? NUM_CLASSES - 1 : t0);

    for (int k = tid; k < HALF_PAD; k += 256) {
        int g = h * HALF_CW + k;
        bool live = (k < HALF_CW) && (d_used[g] != 0u);
        cwl[k] = live ? d_cwbits[g] : d_cwbits[fb];
    }
    __syncthreads();

    int sub = lane & 15;                         // class-slice within half
    int s   = sbase + wid * 2 + (lane >> 4);     // sample
    uint4 x = d_predbits[s];

    unsigned mn = 0xffffffffu;
    #pragma unroll 8
    for (int k = sub; k < HALF_PAD; k += 16)
        mn = min(mn, ham4(x, cwl[k]));

    #pragma unroll
    for (int off = 1; off < 16; off <<= 1)
        mn = min(mn, __shfl_xor_sync(0xffffffffu, mn, off));

    if (sub == 0) atomicMin(&d_mn[s], mn);

    __threadfence();
    __syncthreads();
    if (tid == 0) {
        int old = atomicAdd(&d_done_min, 1);
        s_last = (old == NB_MIN - 1);
    }
    __syncthreads();

    // --- last block: final reduction + output + state reset ---
    if (s_last) {
        float fbce = 0.0f;
        for (int i = tid; i < NB_MAIN; i += 256) fbce += d_bce_part[i];
        unsigned sg = 0u;
        for (int i = tid; i < N_SAMPLES; i += 256) sg += d_mn[i];
        #pragma unroll
        for (int off = 16; off > 0; off >>= 1) {
            fbce += __shfl_down_sync(0xffffffffu, fbce, off);
            sg   += __shfl_down_sync(0xffffffffu, sg, off);
        }
        if (lane == 0) { fred[wid] = fbce; ured[wid] = sg; }
        __syncthreads();
        if (tid == 0) {
            float ftot = 0.0f; unsigned stot = 0;
            #pragma unroll
            for (int w = 0; w < 8; w++) { ftot += fred[w]; stot += ured[w]; }
            out[0] = (ftot + (float)CODE_LEN * (float)stot)
                   / (float)(N_SAMPLES * CODE_LEN);
            d_done_min = 0;                      // reset for next replay
        }
        for (int c = tid; c < NUM_CLASSES; c += 256)
            d_used[c] = 0u;                      // reset (safe: every block read
                                                 // d_used before its d_done inc)
        // d_mn is re-initialized by k_main next replay
    }
}

// ---------------------------------------------------------------------------
extern "C" void kernel_launch(void* const* d_in, const int* in_sizes, int n_in,
                              void* d_out, int out_size) {
    const float* out_p = (const float*)d_in[0];   // [8192,128] float32
    const float* cw_p  = (const float*)d_in[1];   // [1000,128] float32
    const int*   tgt_p = (const int*)d_in[2];     // [8192] int32

    k_main<<<NB_MAIN, 256>>>(out_p, cw_p, tgt_p);
    k_min<<<NB_MIN, 256>>>((float*)d_out, tgt_p);
}